// round 12
// baseline (speedup 1.0000x reference)
#include <cuda_runtime.h>
#include <cuda_bf16.h>
#include <cstdint>

// ---------------------------------------------------------------------------
// DeltaOnlyModel: B=256, L=2048, H=V=64.
// Encoder collapses to 64-entry vocab tables. Scan: 1 block/batch, 64 threads.
// NO M-matvec in the loop: thread-private pred cache pc[c] = M_row_i . k_c and
// readout cache rq[c] = M_row_i . q_c, both rank-1-updated via Gram rows on
// gated steps only. Quad chunking + exact in-quad gate algebra (R11).
// ---------------------------------------------------------------------------

#define H 64
#define V 64
#define L 2048
#define B 256

__device__ float g_ktab[V * H];
__device__ float g_vtab[V * H];
__device__ float g_qtab[V * H];
__device__ float g_gram[V * V];    // G[a][b]  = k_a . k_b
__device__ float g_gramq[V * V];   // Gq[a][b] = k_a . q_b
__device__ float g_thr2[V];

typedef unsigned long long ull;

__device__ __forceinline__ ull ffma2(ull a, ull b, ull c) {
    ull d;
    asm("fma.rn.f32x2 %0, %1, %2, %3;" : "=l"(d) : "l"(a), "l"(b), "l"(c));
    return d;
}
__device__ __forceinline__ ull fadd2(ull a, ull b) {
    ull d;
    asm("add.rn.f32x2 %0, %1, %2;" : "=l"(d) : "l"(a), "l"(b));
    return d;
}
__device__ __forceinline__ ull pack2(float lo, float hi) {
    ull d;
    asm("mov.b64 %0, {%1, %2};" : "=l"(d) : "f"(lo), "f"(hi));
    return d;
}
__device__ __forceinline__ void unpack2(ull a, float& lo, float& hi) {
    asm("mov.b64 {%0, %1}, %2;" : "=f"(lo), "=f"(hi) : "l"(a));
}

// ---------------------------------------------------------------------------
// Table builder: one block per vocab entry, 64 threads.
// ---------------------------------------------------------------------------
__global__ void build_tables(const float* __restrict__ embed,
                             const float* __restrict__ w1,
                             const float* __restrict__ b1,
                             const float* __restrict__ w2,
                             const float* __restrict__ b2,
                             const float* __restrict__ ln_g,
                             const float* __restrict__ ln_b,
                             const float* __restrict__ wk,
                             const float* __restrict__ wv,
                             const float* __restrict__ wq) {
    __shared__ float se[H];
    __shared__ float su[2 * H];
    __shared__ float sh[H];
    __shared__ float sred[H];

    const int c = blockIdx.x;
    const int j = threadIdx.x;

    se[j] = embed[c * H + j];
    __syncthreads();

    #pragma unroll
    for (int rep = 0; rep < 2; rep++) {
        const int m = j + rep * H;
        float a = b1[m];
        #pragma unroll 8
        for (int i = 0; i < H; i++) a = fmaf(se[i], w1[i * (2 * H) + m], a);
        su[m] = fmaxf(a, 0.0f);
    }
    __syncthreads();

    float f = b2[j];
    #pragma unroll 8
    for (int m = 0; m < 2 * H; m++) f = fmaf(su[m], w2[m * H + j], f);

    const float s = se[j] + f;
    sh[j] = s;
    __syncthreads();

    float mu = 0.0f;
    #pragma unroll 8
    for (int i = 0; i < H; i++) mu += sh[i];
    mu *= (1.0f / H);
    float var = 0.0f;
    #pragma unroll 8
    for (int i = 0; i < H; i++) { float d = sh[i] - mu; var = fmaf(d, d, var); }
    var *= (1.0f / H);
    const float hn = (s - mu) * rsqrtf(var + 1e-5f) * ln_g[j] + ln_b[j];
    __syncthreads();
    sh[j] = hn;
    __syncthreads();

    float kr = 0.0f;
    #pragma unroll 8
    for (int i = 0; i < H; i++) kr = fmaf(sh[i], wk[i * H + j], kr);
    sred[j] = kr * kr;
    __syncthreads();
    float nk = 0.0f;
    #pragma unroll 8
    for (int i = 0; i < H; i++) nk += sred[i];
    nk = fmaxf(sqrtf(nk), 1e-12f);
    g_ktab[c * H + j] = kr / nk;
    __syncthreads();

    float vr = 0.0f;
    #pragma unroll 8
    for (int i = 0; i < H; i++) vr = fmaf(sh[i], wv[i * H + j], vr);
    g_vtab[c * H + j] = vr;
    sred[j] = vr * vr;
    __syncthreads();
    float nv = 0.0f;
    #pragma unroll 8
    for (int i = 0; i < H; i++) nv += sred[i];
    if (j == 0) g_thr2[c] = 0.16f * nv;

    float qr = 0.0f;
    #pragma unroll 8
    for (int i = 0; i < H; i++) qr = fmaf(sh[i], wq[i * H + j], qr);
    g_qtab[c * H + j] = qr;
}

// Gram matrices: G[a][b] = k_a.k_b ; Gq[a][b] = k_a.q_b
__global__ void gram_kernel() {
    __shared__ float ka[H];
    const int a = blockIdx.x;
    const int j = threadIdx.x;
    ka[j] = g_ktab[a * H + j];
    __syncthreads();
    float s = 0.0f, sq = 0.0f;
    #pragma unroll 8
    for (int i = 0; i < H; i++) {
        s  = fmaf(ka[i], g_ktab[j * H + i], s);
        sq = fmaf(ka[i], g_qtab[j * H + i], sq);
    }
    g_gram[a * H + j]  = s;
    g_gramq[a * H + j] = sq;
}

// ---------------------------------------------------------------------------
// Scan kernel: quad-chunked with thread-private pred / readout caches.
// ---------------------------------------------------------------------------
#define PCW 68   // cache row stride in floats (16B-aligned, low-conflict)

__global__ __launch_bounds__(64) void scan_kernel(const int* __restrict__ x,
                                                  const float* __restrict__ wo,
                                                  const float* __restrict__ bo,
                                                  float* __restrict__ out) {
    __shared__ __align__(16) float sG[V * V];    // 16 KB Gram (k.k)
    __shared__ __align__(16) float sGq[V * V];   // 16 KB Gram (k.q)
    __shared__ __align__(16) float spc[64 * PCW]; // pred cache, row per thread
    __shared__ __align__(16) float sq[64 * PCW];  // readout cache, row per thread
    __shared__ float sthr[V];
    __shared__ int   sx[L];                      // 8 KB tokens
    __shared__ ull   sxA[2][2][5];               // [parity][warp][5 packed sums]
    __shared__ float sfin[H];

    const int b    = blockIdx.x;
    const int tid  = threadIdx.x;
    const int lane = tid & 31;
    const int w    = tid >> 5;

    for (int i = tid; i < V * V; i += 64) {
        sG[i]  = g_gram[i];
        sGq[i] = g_gramq[i];
    }
    sthr[tid] = g_thr2[tid];
    const int* xb = x + b * L;
    for (int i = tid; i < L; i += 64) sx[i] = xb[i];

    float* pcrow = spc + tid * PCW;
    float* sqrow = sq  + tid * PCW;
    {
        float4 z = make_float4(0.f, 0.f, 0.f, 0.f);
        #pragma unroll
        for (int j = 0; j < PCW / 4; j++) {
            reinterpret_cast<float4*>(pcrow)[j] = z;
            reinterpret_cast<float4*>(sqrow)[j] = z;
        }
    }
    __syncthreads();

    // rank-1 cache update: pc[c] += du*G[tok][c], rq[c] += du*Gq[tok][c]
    auto apply = [&](float du, int tok) {
        const ull dd = pack2(du, du);
        const ulonglong2* gr = reinterpret_cast<const ulonglong2*>(sG  + (tok << 6));
        const ulonglong2* gq = reinterpret_cast<const ulonglong2*>(sGq + (tok << 6));
        ulonglong2* pr = reinterpret_cast<ulonglong2*>(pcrow);
        ulonglong2* qr = reinterpret_cast<ulonglong2*>(sqrow);
        #pragma unroll
        for (int j = 0; j < 16; j++) {
            ulonglong2 pc = pr[j];
            const ulonglong2 g = gr[j];
            pc.x = ffma2(dd, g.x, pc.x);
            pc.y = ffma2(dd, g.y, pc.y);
            pr[j] = pc;
            ulonglong2 qc = qr[j];
            const ulonglong2 h = gq[j];
            qc.x = ffma2(dd, h.x, qc.x);
            qc.y = ffma2(dd, h.y, qc.y);
            qr[j] = qc;
        }
    };

    // prefetch first quad
    int tok0 = sx[0], tok1 = sx[1], tok2 = sx[2], tok3 = sx[3];
    float v0 = g_vtab[(tok0 << 6) + tid];
    float v1 = g_vtab[(tok1 << 6) + tid];
    float v2 = g_vtab[(tok2 << 6) + tid];
    float v3 = g_vtab[(tok3 << 6) + tid];

    for (int t = 0; t < L; t += 4) {
        // preds from private cache (1 LDS each)
        const float P0 = pcrow[tok0];
        const float P1 = pcrow[tok1];
        const float P2 = pcrow[tok2];
        const float P3 = pcrow[tok3];

        // prefetch next quad (tokens + v via L2)
        const int nt = (t + 4) & (L - 1);
        const int nk0 = sx[nt], nk1 = sx[nt + 1], nk2 = sx[nt + 2], nk3 = sx[nt + 3];
        const float nv0 = g_vtab[(nk0 << 6) + tid];
        const float nv1 = g_vtab[(nk1 << 6) + tid];
        const float nv2 = g_vtab[(nk2 << 6) + tid];
        const float nv3 = g_vtab[(nk3 << 6) + tid];

        // gate-chain scalars (issued early, consumed after exchange)
        const float thr0 = sthr[tok0], thr1 = sthr[tok1];
        const float thr2 = sthr[tok2], thr3 = sthr[tok3];
        const float G01 = sG[(tok0 << 6) + tok1];
        const float G02 = sG[(tok0 << 6) + tok2];
        const float G03 = sG[(tok0 << 6) + tok3];
        const float G12 = sG[(tok1 << 6) + tok2];
        const float G13 = sG[(tok1 << 6) + tok3];
        const float G23 = sG[(tok2 << 6) + tok3];

        const float r0 = v0 - P0;
        const float r1 = v1 - P1;
        const float r2 = v2 - P2;
        const float r3 = v3 - P3;

        // 10 dot products packed as 5 f32x2, single butterfly phase
        ull u0 = pack2(r0 * r0, r0 * r1);
        ull u1 = pack2(r0 * r2, r0 * r3);
        ull u2 = pack2(r1 * r1, r1 * r2);
        ull u3 = pack2(r1 * r3, r2 * r2);
        ull u4 = pack2(r2 * r3, r3 * r3);
        #pragma unroll
        for (int o = 16; o > 0; o >>= 1) {
            u0 = fadd2(u0, __shfl_xor_sync(0xffffffffu, u0, o));
            u1 = fadd2(u1, __shfl_xor_sync(0xffffffffu, u1, o));
            u2 = fadd2(u2, __shfl_xor_sync(0xffffffffu, u2, o));
            u3 = fadd2(u3, __shfl_xor_sync(0xffffffffu, u3, o));
            u4 = fadd2(u4, __shfl_xor_sync(0xffffffffu, u4, o));
        }
        const int pb = (t >> 2) & 1;
        if (lane == 0) {
            sxA[pb][w][0] = u0; sxA[pb][w][1] = u1; sxA[pb][w][2] = u2;
            sxA[pb][w][3] = u3; sxA[pb][w][4] = u4;
        }
        __syncthreads();
        float S00, S01, S02, S03, S11, S12, S13, S22, S23, S33;
        unpack2(fadd2(sxA[pb][0][0], sxA[pb][1][0]), S00, S01);
        unpack2(fadd2(sxA[pb][0][1], sxA[pb][1][1]), S02, S03);
        unpack2(fadd2(sxA[pb][0][2], sxA[pb][1][2]), S11, S12);
        unpack2(fadd2(sxA[pb][0][3], sxA[pb][1][3]), S13, S22);
        unpack2(fadd2(sxA[pb][0][4], sxA[pb][1][4]), S23, S33);

        // exact in-quad gate algebra (validated in R3/R11)
        const bool g0 = S00 > thr0;
        const float w10 = g0 ? -G01 : 0.0f;
        const float n1s = S11 + w10 * (2.0f * S01 + w10 * S00);
        const bool g1 = n1s > thr1;
        const float w21 = g1 ? -G12 : 0.0f;
        const float w20 = (g0 ? -G02 : 0.0f) + w21 * w10;
        const float n2s = S22 + w20 * (w20 * S00 + 2.0f * S02)
                              + w21 * (w21 * S11 + 2.0f * S12)
                              + 2.0f * w20 * w21 * S01;
        const bool g2 = n2s > thr2;
        const float w32 = g2 ? -G23 : 0.0f;
        const float t13 = g1 ? -G13 : 0.0f;
        const float w31 = t13 + w32 * w21;
        const float w30 = (g0 ? -G03 : 0.0f) + t13 * w10 + w32 * w20;
        const float n3s = S33 + w30 * (w30 * S00 + 2.0f * S03)
                              + w31 * (w31 * S11 + 2.0f * S13)
                              + w32 * (w32 * S22 + 2.0f * S23)
                              + 2.0f * (w30 * w31 * S01 + w30 * w32 * S02 + w31 * w32 * S12);
        const bool g3 = n3s > thr3;

        // gated rank-1 cache updates (thread-private, no sync needed)
        if (g0) apply(r0, tok0);
        if (g1) apply(fmaf(w10, r0, r1), tok1);
        if (g2) apply(r2 + w20 * r0 + w21 * r1, tok2);
        if (g3) apply(r3 + w30 * r0 + w31 * r1 + w32 * r2, tok3);

        tok0 = nk0; tok1 = nk1; tok2 = nk2; tok3 = nk3;
        v0 = nv0; v1 = nv1; v2 = nv2; v3 = nv3;
    }

    // Readout straight from the rq cache: read = relu(M q) = relu(rq[tokL])
    const int tokL = sx[L - 1];
    sfin[tid] = fmaxf(sqrow[tokL], 0.0f);
    __syncthreads();

    float oacc = bo[tid];
    #pragma unroll 8
    for (int i = 0; i < H; i++) oacc = fmaf(sfin[i], wo[(i << 6) + tid], oacc);
    out[(b << 6) + tid] = oacc;
}

// ---------------------------------------------------------------------------
// Inputs: x, embed, w1, b1, w2, b2, ln_g, ln_b, wk, wv, wq, wo, bo
// ---------------------------------------------------------------------------
extern "C" void kernel_launch(void* const* d_in, const int* in_sizes, int n_in,
                              void* d_out, int out_size) {
    const int*   x     = (const int*)d_in[0];
    const float* embed = (const float*)d_in[1];
    const float* w1    = (const float*)d_in[2];
    const float* b1    = (const float*)d_in[3];
    const float* w2    = (const float*)d_in[4];
    const float* b2    = (const float*)d_in[5];
    const float* ln_g  = (const float*)d_in[6];
    const float* ln_b  = (const float*)d_in[7];
    const float* wk    = (const float*)d_in[8];
    const float* wv    = (const float*)d_in[9];
    const float* wq    = (const float*)d_in[10];
    const float* wo    = (const float*)d_in[11];
    const float* bo    = (const float*)d_in[12];
    float*       out   = (float*)d_out;

    build_tables<<<V, H>>>(embed, w1, b1, w2, b2, ln_g, ln_b, wk, wv, wq);
    gram_kernel<<<V, H>>>();
    scan_kernel<<<B, H>>>(x, wo, bo, out);
}

// round 13
// speedup vs baseline: 1.7733x; 1.7733x over previous
#include <cuda_runtime.h>
#include <cuda_bf16.h>
#include <cstdint>

// ---------------------------------------------------------------------------
// DeltaOnlyModel: B=256, L=2048, H=V=64.
// Encoder collapses to 64-entry vocab tables + key Gram matrix.
// Scan: 1 block/batch, 128 threads: thread (row=tid>>1, half=tid&1) owns 32
// columns of M row `row` in registers. Lane-pair shfl combines pred halves;
// quad chunking + one butterfly/exchange per quad + exact in-quad gate algebra
// (R11, validated). All S sums carry a uniform x2 (lane-pair duplication),
// compensated by doubling the thresholds (gate algebra is S-homogeneous).
// ---------------------------------------------------------------------------

#define H 64
#define V 64
#define L 2048
#define B 256
#define SKW 72   // smem k row stride (words); upper half at +36 => bank-skewed

__device__ float g_ktab[V * H];
__device__ float g_vtab[V * H];
__device__ float g_qtab[V * H];
__device__ float g_gram[V * V];
__device__ float g_thr2[V];

typedef unsigned long long ull;

__device__ __forceinline__ ull ffma2(ull a, ull b, ull c) {
    ull d;
    asm("fma.rn.f32x2 %0, %1, %2, %3;" : "=l"(d) : "l"(a), "l"(b), "l"(c));
    return d;
}
__device__ __forceinline__ ull fadd2(ull a, ull b) {
    ull d;
    asm("add.rn.f32x2 %0, %1, %2;" : "=l"(d) : "l"(a), "l"(b));
    return d;
}
__device__ __forceinline__ ull pack2(float lo, float hi) {
    ull d;
    asm("mov.b64 %0, {%1, %2};" : "=l"(d) : "f"(lo), "f"(hi));
    return d;
}
__device__ __forceinline__ void unpack2(ull a, float& lo, float& hi) {
    asm("mov.b64 {%0, %1}, %2;" : "=f"(lo), "=f"(hi) : "l"(a));
}
__device__ __forceinline__ ull hsum4p(ull a0, ull a1, ull a2, ull a3) {
    return fadd2(fadd2(a0, a1), fadd2(a2, a3));
}
__device__ __forceinline__ float hsum4(ull a0, ull a1, ull a2, ull a3) {
    float lo, hi;
    unpack2(hsum4p(a0, a1, a2, a3), lo, hi);
    return lo + hi;
}

// ---------------------------------------------------------------------------
// Table builder: one block per vocab entry, 64 threads.
// ---------------------------------------------------------------------------
__global__ void build_tables(const float* __restrict__ embed,
                             const float* __restrict__ w1,
                             const float* __restrict__ b1,
                             const float* __restrict__ w2,
                             const float* __restrict__ b2,
                             const float* __restrict__ ln_g,
                             const float* __restrict__ ln_b,
                             const float* __restrict__ wk,
                             const float* __restrict__ wv,
                             const float* __restrict__ wq) {
    __shared__ float se[H];
    __shared__ float su[2 * H];
    __shared__ float sh[H];
    __shared__ float sred[H];

    const int c = blockIdx.x;
    const int j = threadIdx.x;

    se[j] = embed[c * H + j];
    __syncthreads();

    #pragma unroll
    for (int rep = 0; rep < 2; rep++) {
        const int m = j + rep * H;
        float a = b1[m];
        #pragma unroll 8
        for (int i = 0; i < H; i++) a = fmaf(se[i], w1[i * (2 * H) + m], a);
        su[m] = fmaxf(a, 0.0f);
    }
    __syncthreads();

    float f = b2[j];
    #pragma unroll 8
    for (int m = 0; m < 2 * H; m++) f = fmaf(su[m], w2[m * H + j], f);

    const float s = se[j] + f;
    sh[j] = s;
    __syncthreads();

    float mu = 0.0f;
    #pragma unroll 8
    for (int i = 0; i < H; i++) mu += sh[i];
    mu *= (1.0f / H);
    float var = 0.0f;
    #pragma unroll 8
    for (int i = 0; i < H; i++) { float d = sh[i] - mu; var = fmaf(d, d, var); }
    var *= (1.0f / H);
    const float hn = (s - mu) * rsqrtf(var + 1e-5f) * ln_g[j] + ln_b[j];
    __syncthreads();
    sh[j] = hn;
    __syncthreads();

    float kr = 0.0f;
    #pragma unroll 8
    for (int i = 0; i < H; i++) kr = fmaf(sh[i], wk[i * H + j], kr);
    sred[j] = kr * kr;
    __syncthreads();
    float nk = 0.0f;
    #pragma unroll 8
    for (int i = 0; i < H; i++) nk += sred[i];
    nk = fmaxf(sqrtf(nk), 1e-12f);
    g_ktab[c * H + j] = kr / nk;
    __syncthreads();

    float vr = 0.0f;
    #pragma unroll 8
    for (int i = 0; i < H; i++) vr = fmaf(sh[i], wv[i * H + j], vr);
    g_vtab[c * H + j] = vr;
    sred[j] = vr * vr;
    __syncthreads();
    float nv = 0.0f;
    #pragma unroll 8
    for (int i = 0; i < H; i++) nv += sred[i];
    if (j == 0) g_thr2[c] = 0.16f * nv;

    float qr = 0.0f;
    #pragma unroll 8
    for (int i = 0; i < H; i++) qr = fmaf(sh[i], wq[i * H + j], qr);
    g_qtab[c * H + j] = qr;
}

// Gram matrix of normalized keys: G[a][b] = k_a . k_b
__global__ void gram_kernel() {
    __shared__ float ka[H];
    const int a = blockIdx.x;
    const int j = threadIdx.x;
    ka[j] = g_ktab[a * H + j];
    __syncthreads();
    float s = 0.0f;
    #pragma unroll 8
    for (int i = 0; i < H; i++) s = fmaf(ka[i], g_ktab[j * H + i], s);
    g_gram[a * H + j] = s;
}

// ---------------------------------------------------------------------------
// Scan kernel: 128 threads, half-row per thread, quad-chunked.
// ---------------------------------------------------------------------------
__global__ __launch_bounds__(128) void scan_kernel(const int* __restrict__ x,
                                                   const float* __restrict__ wo,
                                                   const float* __restrict__ bo,
                                                   float* __restrict__ out) {
    __shared__ __align__(16) float sk[V * SKW];  // 18 KB k, bank-skewed halves
    __shared__ float sv[V * H];                  // 16 KB v table
    __shared__ float sG[V * V];                  // 16 KB Gram
    __shared__ float sthr[V];
    __shared__ int   sx[L];                      // 8 KB tokens
    __shared__ ull   sxch[2][4][5];              // [parity][warp][5 packed sums]
    __shared__ float sfin[H];

    const int b    = blockIdx.x;
    const int tid  = threadIdx.x;
    const int lane = tid & 31;
    const int w    = tid >> 5;
    const int row  = tid >> 1;
    const int half = tid & 1;
    const int cb   = half ? 36 : 0;              // k base word within row

    // load tables (k gets the skewed layout)
    for (int i = tid; i < V * H; i += 128) {
        const int c   = i >> 6;
        const int col = i & 63;
        sk[c * SKW + (col < 32 ? col : col + 4)] = g_ktab[i];
        sv[i] = g_vtab[i];
    }
    for (int i = tid; i < V * V; i += 128) sG[i] = g_gram[i];
    if (tid < V) sthr[tid] = g_thr2[tid];
    const int* xb = x + b * L;
    for (int i = tid; i < L; i += 128) sx[i] = xb[i];
    __syncthreads();

    // 32 columns of M row `row`: 16 packed f32x2 registers.
    ull m2[16];
    #pragma unroll
    for (int i = 0; i < 16; i++) m2[i] = 0ULL;

    for (int t = 0; t < L; t += 4) {
        const int tok0 = sx[t];
        const int tok1 = sx[t + 1];
        const int tok2 = sx[t + 2];
        const int tok3 = sx[t + 3];

        // scalars (broadcast); thresholds doubled to absorb lane-pair x2 on S
        const float thr0 = 2.0f * sthr[tok0], thr1 = 2.0f * sthr[tok1];
        const float thr2 = 2.0f * sthr[tok2], thr3 = 2.0f * sthr[tok3];
        const float G01 = sG[(tok0 << 6) + tok1];
        const float G02 = sG[(tok0 << 6) + tok2];
        const float G03 = sG[(tok0 << 6) + tok3];
        const float G12 = sG[(tok1 << 6) + tok2];
        const float G13 = sG[(tok1 << 6) + tok3];
        const float G23 = sG[(tok2 << 6) + tok3];
        const float v0 = sv[(tok0 << 6) + row];
        const float v1 = sv[(tok1 << 6) + row];
        const float v2 = sv[(tok2 << 6) + row];
        const float v3 = sv[(tok3 << 6) + row];

        const ulonglong2* kp0 = reinterpret_cast<const ulonglong2*>(sk + tok0 * SKW + cb);
        const ulonglong2* kp1 = reinterpret_cast<const ulonglong2*>(sk + tok1 * SKW + cb);
        const ulonglong2* kp2 = reinterpret_cast<const ulonglong2*>(sk + tok2 * SKW + cb);
        const ulonglong2* kp3 = reinterpret_cast<const ulonglong2*>(sk + tok3 * SKW + cb);

        // half-row pred partials for the four tokens
        ull a0 = 0, a1 = 0, a2 = 0, a3 = 0;
        ull c0 = 0, c1 = 0, c2 = 0, c3 = 0;
        ull e0 = 0, e1 = 0, e2 = 0, e3 = 0;
        ull f0 = 0, f1 = 0, f2 = 0, f3 = 0;
        #pragma unroll
        for (int j = 0; j < 4; j++) {
            const ulonglong2 kA0 = kp0[2 * j], kB0 = kp0[2 * j + 1];
            const ulonglong2 kA1 = kp1[2 * j], kB1 = kp1[2 * j + 1];
            const ulonglong2 kA2 = kp2[2 * j], kB2 = kp2[2 * j + 1];
            const ulonglong2 kA3 = kp3[2 * j], kB3 = kp3[2 * j + 1];
            const ull m0 = m2[4 * j + 0], m1 = m2[4 * j + 1];
            const ull mm2 = m2[4 * j + 2], m3 = m2[4 * j + 3];
            a0 = ffma2(m0, kA0.x, a0); a1 = ffma2(m1, kA0.y, a1);
            a2 = ffma2(mm2, kB0.x, a2); a3 = ffma2(m3, kB0.y, a3);
            c0 = ffma2(m0, kA1.x, c0); c1 = ffma2(m1, kA1.y, c1);
            c2 = ffma2(mm2, kB1.x, c2); c3 = ffma2(m3, kB1.y, c3);
            e0 = ffma2(m0, kA2.x, e0); e1 = ffma2(m1, kA2.y, e1);
            e2 = ffma2(mm2, kB2.x, e2); e3 = ffma2(m3, kB2.y, e3);
            f0 = ffma2(m0, kA3.x, f0); f1 = ffma2(m1, kA3.y, f1);
            f2 = ffma2(mm2, kB3.x, f2); f3 = ffma2(m3, kB3.y, f3);
        }
        const float pp0 = hsum4(a0, a1, a2, a3);
        const float pp1 = hsum4(c0, c1, c2, c3);
        const float pp2 = hsum4(e0, e1, e2, e3);
        const float pp3 = hsum4(f0, f1, f2, f3);

        // combine the two column-halves within the lane pair (1 ull-shfl each)
        ull u01 = pack2(pp0, pp1);
        ull u23 = pack2(pp2, pp3);
        u01 = fadd2(u01, __shfl_xor_sync(0xffffffffu, u01, 1));
        u23 = fadd2(u23, __shfl_xor_sync(0xffffffffu, u23, 1));
        float P0, P1, P2, P3;
        unpack2(u01, P0, P1);
        unpack2(u23, P2, P3);

        const float r0 = v0 - P0;
        const float r1 = v1 - P1;
        const float r2 = v2 - P2;
        const float r3 = v3 - P3;

        // 10 dot products packed as 5 f32x2; butterfly sums each row twice
        ull u0 = pack2(r0 * r0, r0 * r1);
        ull u1 = pack2(r0 * r2, r0 * r3);
        ull u2 = pack2(r1 * r1, r1 * r2);
        ull u3 = pack2(r1 * r3, r2 * r2);
        ull u4 = pack2(r2 * r3, r3 * r3);
        #pragma unroll
        for (int o = 16; o > 0; o >>= 1) {
            u0 = fadd2(u0, __shfl_xor_sync(0xffffffffu, u0, o));
            u1 = fadd2(u1, __shfl_xor_sync(0xffffffffu, u1, o));
            u2 = fadd2(u2, __shfl_xor_sync(0xffffffffu, u2, o));
            u3 = fadd2(u3, __shfl_xor_sync(0xffffffffu, u3, o));
            u4 = fadd2(u4, __shfl_xor_sync(0xffffffffu, u4, o));
        }
        const int pb = (t >> 2) & 1;
        if (lane == 0) {
            sxch[pb][w][0] = u0; sxch[pb][w][1] = u1; sxch[pb][w][2] = u2;
            sxch[pb][w][3] = u3; sxch[pb][w][4] = u4;
        }
        __syncthreads();
        const ull s0 = fadd2(fadd2(sxch[pb][0][0], sxch[pb][1][0]),
                             fadd2(sxch[pb][2][0], sxch[pb][3][0]));
        const ull s1 = fadd2(fadd2(sxch[pb][0][1], sxch[pb][1][1]),
                             fadd2(sxch[pb][2][1], sxch[pb][3][1]));
        const ull s2 = fadd2(fadd2(sxch[pb][0][2], sxch[pb][1][2]),
                             fadd2(sxch[pb][2][2], sxch[pb][3][2]));
        const ull s3 = fadd2(fadd2(sxch[pb][0][3], sxch[pb][1][3]),
                             fadd2(sxch[pb][2][3], sxch[pb][3][3]));
        const ull s4 = fadd2(fadd2(sxch[pb][0][4], sxch[pb][1][4]),
                             fadd2(sxch[pb][2][4], sxch[pb][3][4]));
        float S00, S01, S02, S03, S11, S12, S13, S22, S23, S33;
        unpack2(s0, S00, S01);
        unpack2(s1, S02, S03);
        unpack2(s2, S11, S12);
        unpack2(s3, S13, S22);
        unpack2(s4, S23, S33);

        // exact in-quad gate algebra (homogeneous in S; thr pre-doubled)
        const bool g0 = S00 > thr0;
        const float w10 = g0 ? -G01 : 0.0f;
        const float n1s = S11 + w10 * (2.0f * S01 + w10 * S00);
        const bool g1 = n1s > thr1;
        const float w21 = g1 ? -G12 : 0.0f;
        const float w20 = (g0 ? -G02 : 0.0f) + w21 * w10;
        const float n2s = S22 + w20 * (w20 * S00 + 2.0f * S02)
                              + w21 * (w21 * S11 + 2.0f * S12)
                              + 2.0f * w20 * w21 * S01;
        const bool g2 = n2s > thr2;
        const float w32 = g2 ? -G23 : 0.0f;
        const float t13 = g1 ? -G13 : 0.0f;
        const float w31 = t13 + w32 * w21;
        const float w30 = (g0 ? -G03 : 0.0f) + t13 * w10 + w32 * w20;
        const float n3s = S33 + w30 * (w30 * S00 + 2.0f * S03)
                              + w31 * (w31 * S11 + 2.0f * S13)
                              + w32 * (w32 * S22 + 2.0f * S23)
                              + 2.0f * (w30 * w31 * S01 + w30 * w32 * S02 + w31 * w32 * S12);
        const bool g3 = n3s > thr3;

        if (g0 | g1 | g2 | g3) {
            const float du0 = g0 ? r0 : 0.0f;
            const float du1 = g1 ? (r1 + w10 * r0) : 0.0f;
            const float du2 = g2 ? (r2 + w20 * r0 + w21 * r1) : 0.0f;
            const float du3 = g3 ? (r3 + w30 * r0 + w31 * r1 + w32 * r2) : 0.0f;
            const ull dd0 = pack2(du0, du0);
            const ull dd1 = pack2(du1, du1);
            const ull dd2 = pack2(du2, du2);
            const ull dd3 = pack2(du3, du3);
            #pragma unroll
            for (int j = 0; j < 4; j++) {
                const ulonglong2 kA0 = kp0[2 * j], kB0 = kp0[2 * j + 1];
                const ulonglong2 kA1 = kp1[2 * j], kB1 = kp1[2 * j + 1];
                const ulonglong2 kA2 = kp2[2 * j], kB2 = kp2[2 * j + 1];
                const ulonglong2 kA3 = kp3[2 * j], kB3 = kp3[2 * j + 1];
                m2[4 * j + 0] = ffma2(dd3, kA3.x, ffma2(dd2, kA2.x,
                                 ffma2(dd1, kA1.x, ffma2(dd0, kA0.x, m2[4 * j + 0]))));
                m2[4 * j + 1] = ffma2(dd3, kA3.y, ffma2(dd2, kA2.y,
                                 ffma2(dd1, kA1.y, ffma2(dd0, kA0.y, m2[4 * j + 1]))));
                m2[4 * j + 2] = ffma2(dd3, kB3.x, ffma2(dd2, kB2.x,
                                 ffma2(dd1, kB1.x, ffma2(dd0, kB0.x, m2[4 * j + 2]))));
                m2[4 * j + 3] = ffma2(dd3, kB3.y, ffma2(dd2, kB2.y,
                                 ffma2(dd1, kB1.y, ffma2(dd0, kB0.y, m2[4 * j + 3]))));
            }
        }
    }

    // Readout: half-row dot with q, combine across lane pair, relu.
    const int tokL = sx[L - 1];
    const ulonglong2* qp = reinterpret_cast<const ulonglong2*>(g_qtab + (tokL << 6) + (half << 5));
    ull a0 = 0, a1 = 0, a2 = 0, a3 = 0;
    #pragma unroll
    for (int j = 0; j < 4; j++) {
        const ulonglong2 qA = qp[2 * j];
        const ulonglong2 qB = qp[2 * j + 1];
        a0 = ffma2(m2[4 * j + 0], qA.x, a0);
        a1 = ffma2(m2[4 * j + 1], qA.y, a1);
        a2 = ffma2(m2[4 * j + 2], qB.x, a2);
        a3 = ffma2(m2[4 * j + 3], qB.y, a3);
    }
    float pr = hsum4(a0, a1, a2, a3);
    pr += __shfl_xor_sync(0xffffffffu, pr, 1);
    sfin[row] = fmaxf(pr, 0.0f);   // both lanes write identical value
    __syncthreads();

    if (tid < H) {
        float oacc = bo[tid];
        #pragma unroll 8
        for (int i = 0; i < H; i++) oacc = fmaf(sfin[i], wo[(i << 6) + tid], oacc);
        out[(b << 6) + tid] = oacc;
    }
}

// ---------------------------------------------------------------------------
// Inputs: x, embed, w1, b1, w2, b2, ln_g, ln_b, wk, wv, wq, wo, bo
// ---------------------------------------------------------------------------
extern "C" void kernel_launch(void* const* d_in, const int* in_sizes, int n_in,
                              void* d_out, int out_size) {
    const int*   x     = (const int*)d_in[0];
    const float* embed = (const float*)d_in[1];
    const float* w1    = (const float*)d_in[2];
    const float* b1    = (const float*)d_in[3];
    const float* w2    = (const float*)d_in[4];
    const float* b2    = (const float*)d_in[5];
    const float* ln_g  = (const float*)d_in[6];
    const float* ln_b  = (const float*)d_in[7];
    const float* wk    = (const float*)d_in[8];
    const float* wv    = (const float*)d_in[9];
    const float* wq    = (const float*)d_in[10];
    const float* wo    = (const float*)d_in[11];
    const float* bo    = (const float*)d_in[12];
    float*       out   = (float*)d_out;

    build_tables<<<V, H>>>(embed, w1, b1, w2, b2, ln_g, ln_b, wk, wv, wq);
    gram_kernel<<<V, H>>>();
    scan_kernel<<<B, 128>>>(x, wo, bo, out);
}

// round 14
// speedup vs baseline: 2.1840x; 1.2316x over previous
#include <cuda_runtime.h>
#include <cuda_bf16.h>
#include <cstdint>

// ---------------------------------------------------------------------------
// DeltaOnlyModel: B=256, L=2048, H=V=64.
// Encoder collapses to 64-entry vocab tables + key Gram matrix.
// Scan: 1 block/batch, 64 threads, M row/thread in registers, quad chunking
// with exact in-quad gate algebra (R11) + CROSS-QUAD SPECULATION: next-quad
// preds are computed against pre-update M inside the butterfly/exchange stall
// window and corrected exactly via 16 Gram FMAs once the gates are known.
// ---------------------------------------------------------------------------

#define H 64
#define V 64
#define L 2048
#define B 256

__device__ float g_ktab[V * H];
__device__ float g_vtab[V * H];
__device__ float g_qtab[V * H];
__device__ float g_gram[V * V];
__device__ float g_thr2[V];

typedef unsigned long long ull;

__device__ __forceinline__ ull ffma2(ull a, ull b, ull c) {
    ull d;
    asm("fma.rn.f32x2 %0, %1, %2, %3;" : "=l"(d) : "l"(a), "l"(b), "l"(c));
    return d;
}
__device__ __forceinline__ ull fadd2(ull a, ull b) {
    ull d;
    asm("add.rn.f32x2 %0, %1, %2;" : "=l"(d) : "l"(a), "l"(b));
    return d;
}
__device__ __forceinline__ ull pack2(float lo, float hi) {
    ull d;
    asm("mov.b64 %0, {%1, %2};" : "=l"(d) : "f"(lo), "f"(hi));
    return d;
}
__device__ __forceinline__ void unpack2(ull a, float& lo, float& hi) {
    asm("mov.b64 {%0, %1}, %2;" : "=f"(lo), "=f"(hi) : "l"(a));
}
__device__ __forceinline__ float hsum4(ull a0, ull a1, ull a2, ull a3) {
    float lo, hi;
    unpack2(fadd2(fadd2(a0, a1), fadd2(a2, a3)), lo, hi);
    return lo + hi;
}

// ---------------------------------------------------------------------------
// Table builder: one block per vocab entry, 64 threads.
// ---------------------------------------------------------------------------
__global__ void build_tables(const float* __restrict__ embed,
                             const float* __restrict__ w1,
                             const float* __restrict__ b1,
                             const float* __restrict__ w2,
                             const float* __restrict__ b2,
                             const float* __restrict__ ln_g,
                             const float* __restrict__ ln_b,
                             const float* __restrict__ wk,
                             const float* __restrict__ wv,
                             const float* __restrict__ wq) {
    __shared__ float se[H];
    __shared__ float su[2 * H];
    __shared__ float sh[H];
    __shared__ float sred[H];

    const int c = blockIdx.x;
    const int j = threadIdx.x;

    se[j] = embed[c * H + j];
    __syncthreads();

    #pragma unroll
    for (int rep = 0; rep < 2; rep++) {
        const int m = j + rep * H;
        float a = b1[m];
        #pragma unroll 8
        for (int i = 0; i < H; i++) a = fmaf(se[i], w1[i * (2 * H) + m], a);
        su[m] = fmaxf(a, 0.0f);
    }
    __syncthreads();

    float f = b2[j];
    #pragma unroll 8
    for (int m = 0; m < 2 * H; m++) f = fmaf(su[m], w2[m * H + j], f);

    const float s = se[j] + f;
    sh[j] = s;
    __syncthreads();

    float mu = 0.0f;
    #pragma unroll 8
    for (int i = 0; i < H; i++) mu += sh[i];
    mu *= (1.0f / H);
    float var = 0.0f;
    #pragma unroll 8
    for (int i = 0; i < H; i++) { float d = sh[i] - mu; var = fmaf(d, d, var); }
    var *= (1.0f / H);
    const float hn = (s - mu) * rsqrtf(var + 1e-5f) * ln_g[j] + ln_b[j];
    __syncthreads();
    sh[j] = hn;
    __syncthreads();

    float kr = 0.0f;
    #pragma unroll 8
    for (int i = 0; i < H; i++) kr = fmaf(sh[i], wk[i * H + j], kr);
    sred[j] = kr * kr;
    __syncthreads();
    float nk = 0.0f;
    #pragma unroll 8
    for (int i = 0; i < H; i++) nk += sred[i];
    nk = fmaxf(sqrtf(nk), 1e-12f);
    g_ktab[c * H + j] = kr / nk;
    __syncthreads();

    float vr = 0.0f;
    #pragma unroll 8
    for (int i = 0; i < H; i++) vr = fmaf(sh[i], wv[i * H + j], vr);
    g_vtab[c * H + j] = vr;
    sred[j] = vr * vr;
    __syncthreads();
    float nv = 0.0f;
    #pragma unroll 8
    for (int i = 0; i < H; i++) nv += sred[i];
    if (j == 0) g_thr2[c] = 0.16f * nv;

    float qr = 0.0f;
    #pragma unroll 8
    for (int i = 0; i < H; i++) qr = fmaf(sh[i], wq[i * H + j], qr);
    g_qtab[c * H + j] = qr;
}

// Gram matrix of normalized keys: G[a][b] = k_a . k_b
__global__ void gram_kernel() {
    __shared__ float ka[H];
    const int a = blockIdx.x;
    const int j = threadIdx.x;
    ka[j] = g_ktab[a * H + j];
    __syncthreads();
    float s = 0.0f;
    #pragma unroll 8
    for (int i = 0; i < H; i++) s = fmaf(ka[i], g_ktab[j * H + i], s);
    g_gram[a * H + j] = s;
}

// ---------------------------------------------------------------------------
// Scan kernel: quad-chunked + cross-quad speculative preds.
// ---------------------------------------------------------------------------
__global__ __launch_bounds__(64) void scan_kernel(const int* __restrict__ x,
                                                  const float* __restrict__ wo,
                                                  const float* __restrict__ bo,
                                                  float* __restrict__ out) {
    __shared__ __align__(16) float sk[V * H];   // 16 KB normalized k
    __shared__ float sv[V * H];                 // 16 KB v table
    __shared__ float sG[V * V];                 // 16 KB Gram
    __shared__ float sthr[V];
    __shared__ int   sx[L];                     // 8 KB tokens
    __shared__ ull   sxA[2][2][5];              // [parity][warp][5 packed sums]
    __shared__ float sfin[H];

    const int b    = blockIdx.x;
    const int tid  = threadIdx.x;
    const int lane = tid & 31;
    const int w    = tid >> 5;

    for (int i = tid; i < V * H; i += 64) {
        sk[i] = g_ktab[i];
        sv[i] = g_vtab[i];
        sG[i] = g_gram[i];
    }
    sthr[tid] = g_thr2[tid];
    const int* xb = x + b * L;
    for (int i = tid; i < L; i += 64) sx[i] = xb[i];
    __syncthreads();

    ull m2[32];
    #pragma unroll
    for (int i = 0; i < 32; i++) m2[i] = 0ULL;

    // current quad state (preds exact vs current M; M=0 initially)
    int tk0 = sx[0], tk1 = sx[1], tk2 = sx[2], tk3 = sx[3];
    float vv0 = sv[(tk0 << 6) + tid];
    float vv1 = sv[(tk1 << 6) + tid];
    float vv2 = sv[(tk2 << 6) + tid];
    float vv3 = sv[(tk3 << 6) + tid];
    float P0 = 0.0f, P1 = 0.0f, P2 = 0.0f, P3 = 0.0f;

    for (int t = 0; t < L; t += 4) {
        // next-quad tokens and values (independent prefetch)
        const int nt = (t + 4) & (L - 1);
        const int nk0 = sx[nt], nk1 = sx[nt + 1], nk2 = sx[nt + 2], nk3 = sx[nt + 3];
        const float nv0 = sv[(nk0 << 6) + tid];
        const float nv1 = sv[(nk1 << 6) + tid];
        const float nv2 = sv[(nk2 << 6) + tid];
        const float nv3 = sv[(nk3 << 6) + tid];

        // current-quad gate scalars
        const float thr0 = sthr[tk0], thr1 = sthr[tk1];
        const float thr2 = sthr[tk2], thr3 = sthr[tk3];
        const float G01 = sG[(tk0 << 6) + tk1];
        const float G02 = sG[(tk0 << 6) + tk2];
        const float G03 = sG[(tk0 << 6) + tk3];
        const float G12 = sG[(tk1 << 6) + tk2];
        const float G13 = sG[(tk1 << 6) + tk3];
        const float G23 = sG[(tk2 << 6) + tk3];

        const float r0 = vv0 - P0;
        const float r1 = vv1 - P1;
        const float r2 = vv2 - P2;
        const float r3 = vv3 - P3;

        // 10 dot products packed as 5 f32x2, single butterfly phase
        ull u0 = pack2(r0 * r0, r0 * r1);
        ull u1 = pack2(r0 * r2, r0 * r3);
        ull u2 = pack2(r1 * r1, r1 * r2);
        ull u3 = pack2(r1 * r3, r2 * r2);
        ull u4 = pack2(r2 * r3, r3 * r3);
        #pragma unroll
        for (int o = 16; o > 0; o >>= 1) {
            u0 = fadd2(u0, __shfl_xor_sync(0xffffffffu, u0, o));
            u1 = fadd2(u1, __shfl_xor_sync(0xffffffffu, u1, o));
            u2 = fadd2(u2, __shfl_xor_sync(0xffffffffu, u2, o));
            u3 = fadd2(u3, __shfl_xor_sync(0xffffffffu, u3, o));
            u4 = fadd2(u4, __shfl_xor_sync(0xffffffffu, u4, o));
        }
        const int pb = (t >> 2) & 1;
        if (lane == 0) {
            sxA[pb][w][0] = u0; sxA[pb][w][1] = u1; sxA[pb][w][2] = u2;
            sxA[pb][w][3] = u3; sxA[pb][w][4] = u4;
        }

        // --- speculative preds for NEXT quad vs PRE-update M ---
        // (independent of the butterfly; fills the stall window)
        const ulonglong2* kn0 = reinterpret_cast<const ulonglong2*>(sk + (nk0 << 6));
        const ulonglong2* kn1 = reinterpret_cast<const ulonglong2*>(sk + (nk1 << 6));
        const ulonglong2* kn2 = reinterpret_cast<const ulonglong2*>(sk + (nk2 << 6));
        const ulonglong2* kn3 = reinterpret_cast<const ulonglong2*>(sk + (nk3 << 6));
        ull a0 = 0, a1 = 0, a2 = 0, a3 = 0;
        ull c0 = 0, c1 = 0, c2 = 0, c3 = 0;
        ull e0 = 0, e1 = 0, e2 = 0, e3 = 0;
        ull f0 = 0, f1 = 0, f2 = 0, f3 = 0;
        #pragma unroll
        for (int j = 0; j < 8; j++) {
            const ulonglong2 kA0 = kn0[2 * j], kB0 = kn0[2 * j + 1];
            const ulonglong2 kA1 = kn1[2 * j], kB1 = kn1[2 * j + 1];
            const ulonglong2 kA2 = kn2[2 * j], kB2 = kn2[2 * j + 1];
            const ulonglong2 kA3 = kn3[2 * j], kB3 = kn3[2 * j + 1];
            const ull m0 = m2[4 * j + 0], m1 = m2[4 * j + 1];
            const ull mm2 = m2[4 * j + 2], m3 = m2[4 * j + 3];
            a0 = ffma2(m0, kA0.x, a0); a1 = ffma2(m1, kA0.y, a1);
            a2 = ffma2(mm2, kB0.x, a2); a3 = ffma2(m3, kB0.y, a3);
            c0 = ffma2(m0, kA1.x, c0); c1 = ffma2(m1, kA1.y, c1);
            c2 = ffma2(mm2, kB1.x, c2); c3 = ffma2(m3, kB1.y, c3);
            e0 = ffma2(m0, kA2.x, e0); e1 = ffma2(m1, kA2.y, e1);
            e2 = ffma2(mm2, kB2.x, e2); e3 = ffma2(m3, kB2.y, e3);
            f0 = ffma2(m0, kA3.x, f0); f1 = ffma2(m1, kA3.y, f1);
            f2 = ffma2(mm2, kB3.x, f2); f3 = ffma2(m3, kB3.y, f3);
        }
        float Pn0 = hsum4(a0, a1, a2, a3);
        float Pn1 = hsum4(c0, c1, c2, c3);
        float Pn2 = hsum4(e0, e1, e2, e3);
        float Pn3 = hsum4(f0, f1, f2, f3);

        __syncthreads();
        float S00, S01, S02, S03, S11, S12, S13, S22, S23, S33;
        unpack2(fadd2(sxA[pb][0][0], sxA[pb][1][0]), S00, S01);
        unpack2(fadd2(sxA[pb][0][1], sxA[pb][1][1]), S02, S03);
        unpack2(fadd2(sxA[pb][0][2], sxA[pb][1][2]), S11, S12);
        unpack2(fadd2(sxA[pb][0][3], sxA[pb][1][3]), S13, S22);
        unpack2(fadd2(sxA[pb][0][4], sxA[pb][1][4]), S23, S33);

        // exact in-quad gate algebra (validated R3/R11)
        const bool g0 = S00 > thr0;
        const float w10 = g0 ? -G01 : 0.0f;
        const float n1s = S11 + w10 * (2.0f * S01 + w10 * S00);
        const bool g1 = n1s > thr1;
        const float w21 = g1 ? -G12 : 0.0f;
        const float w20 = (g0 ? -G02 : 0.0f) + w21 * w10;
        const float n2s = S22 + w20 * (w20 * S00 + 2.0f * S02)
                              + w21 * (w21 * S11 + 2.0f * S12)
                              + 2.0f * w20 * w21 * S01;
        const bool g2 = n2s > thr2;
        const float w32 = g2 ? -G23 : 0.0f;
        const float t13 = g1 ? -G13 : 0.0f;
        const float w31 = t13 + w32 * w21;
        const float w30 = (g0 ? -G03 : 0.0f) + t13 * w10 + w32 * w20;
        const float n3s = S33 + w30 * (w30 * S00 + 2.0f * S03)
                              + w31 * (w31 * S11 + 2.0f * S13)
                              + w32 * (w32 * S22 + 2.0f * S23)
                              + 2.0f * (w30 * w31 * S01 + w30 * w32 * S02 + w31 * w32 * S12);
        const bool g3 = n3s > thr3;

        if (g0 | g1 | g2 | g3) {
            const float du0 = g0 ? r0 : 0.0f;
            const float du1 = g1 ? (r1 + w10 * r0) : 0.0f;
            const float du2 = g2 ? (r2 + w20 * r0 + w21 * r1) : 0.0f;
            const float du3 = g3 ? (r3 + w30 * r0 + w31 * r1 + w32 * r2) : 0.0f;
            const ull dd0 = pack2(du0, du0);
            const ull dd1 = pack2(du1, du1);
            const ull dd2 = pack2(du2, du2);
            const ull dd3 = pack2(du3, du3);

            // exact correction of speculative preds: Pn_j += sum_i du_i*G[tk_i][nk_j]
            Pn0 = fmaf(du0, sG[(tk0 << 6) + nk0],
                  fmaf(du1, sG[(tk1 << 6) + nk0],
                  fmaf(du2, sG[(tk2 << 6) + nk0],
                  fmaf(du3, sG[(tk3 << 6) + nk0], Pn0))));
            Pn1 = fmaf(du0, sG[(tk0 << 6) + nk1],
                  fmaf(du1, sG[(tk1 << 6) + nk1],
                  fmaf(du2, sG[(tk2 << 6) + nk1],
                  fmaf(du3, sG[(tk3 << 6) + nk1], Pn1))));
            Pn2 = fmaf(du0, sG[(tk0 << 6) + nk2],
                  fmaf(du1, sG[(tk1 << 6) + nk2],
                  fmaf(du2, sG[(tk2 << 6) + nk2],
                  fmaf(du3, sG[(tk3 << 6) + nk2], Pn2))));
            Pn3 = fmaf(du0, sG[(tk0 << 6) + nk3],
                  fmaf(du1, sG[(tk1 << 6) + nk3],
                  fmaf(du2, sG[(tk2 << 6) + nk3],
                  fmaf(du3, sG[(tk3 << 6) + nk3], Pn3))));

            const ulonglong2* kp0 = reinterpret_cast<const ulonglong2*>(sk + (tk0 << 6));
            const ulonglong2* kp1 = reinterpret_cast<const ulonglong2*>(sk + (tk1 << 6));
            const ulonglong2* kp2 = reinterpret_cast<const ulonglong2*>(sk + (tk2 << 6));
            const ulonglong2* kp3 = reinterpret_cast<const ulonglong2*>(sk + (tk3 << 6));
            #pragma unroll
            for (int j = 0; j < 8; j++) {
                const ulonglong2 kA0 = kp0[2 * j], kB0 = kp0[2 * j + 1];
                const ulonglong2 kA1 = kp1[2 * j], kB1 = kp1[2 * j + 1];
                const ulonglong2 kA2 = kp2[2 * j], kB2 = kp2[2 * j + 1];
                const ulonglong2 kA3 = kp3[2 * j], kB3 = kp3[2 * j + 1];
                m2[4 * j + 0] = ffma2(dd3, kA3.x, ffma2(dd2, kA2.x,
                                 ffma2(dd1, kA1.x, ffma2(dd0, kA0.x, m2[4 * j + 0]))));
                m2[4 * j + 1] = ffma2(dd3, kA3.y, ffma2(dd2, kA2.y,
                                 ffma2(dd1, kA1.y, ffma2(dd0, kA0.y, m2[4 * j + 1]))));
                m2[4 * j + 2] = ffma2(dd3, kB3.x, ffma2(dd2, kB2.x,
                                 ffma2(dd1, kB1.x, ffma2(dd0, kB0.x, m2[4 * j + 2]))));
                m2[4 * j + 3] = ffma2(dd3, kB3.y, ffma2(dd2, kB2.y,
                                 ffma2(dd1, kB1.y, ffma2(dd0, kB0.y, m2[4 * j + 3]))));
            }
        }

        // rotate
        tk0 = nk0; tk1 = nk1; tk2 = nk2; tk3 = nk3;
        vv0 = nv0; vv1 = nv1; vv2 = nv2; vv3 = nv3;
        P0 = Pn0; P1 = Pn1; P2 = Pn2; P3 = Pn3;
    }

    // Readout: q = q_tab[last token]; read = relu(M q); out = read @ wo + bo
    const int tokL = sx[L - 1];
    const float* qv = g_qtab + (tokL << 6);
    float r = 0.0f;
    #pragma unroll
    for (int j = 0; j < 32; j++) {
        float lo, hi;
        unpack2(m2[j], lo, hi);
        r = fmaf(lo, qv[2 * j], r);
        r = fmaf(hi, qv[2 * j + 1], r);
    }
    r = fmaxf(r, 0.0f);
    sfin[tid] = r;
    __syncthreads();

    float oacc = bo[tid];
    #pragma unroll 8
    for (int i = 0; i < H; i++) oacc = fmaf(sfin[i], wo[(i << 6) + tid], oacc);
    out[(b << 6) + tid] = oacc;
}

// ---------------------------------------------------------------------------
// Inputs: x, embed, w1, b1, w2, b2, ln_g, ln_b, wk, wv, wq, wo, bo
// ---------------------------------------------------------------------------
extern "C" void kernel_launch(void* const* d_in, const int* in_sizes, int n_in,
                              void* d_out, int out_size) {
    const int*   x     = (const int*)d_in[0];
    const float* embed = (const float*)d_in[1];
    const float* w1    = (const float*)d_in[2];
    const float* b1    = (const float*)d_in[3];
    const float* w2    = (const float*)d_in[4];
    const float* b2    = (const float*)d_in[5];
    const float* ln_g  = (const float*)d_in[6];
    const float* ln_b  = (const float*)d_in[7];
    const float* wk    = (const float*)d_in[8];
    const float* wv    = (const float*)d_in[9];
    const float* wq    = (const float*)d_in[10];
    const float* wo    = (const float*)d_in[11];
    const float* bo    = (const float*)d_in[12];
    float*       out   = (float*)d_out;

    build_tables<<<V, H>>>(embed, w1, b1, w2, b2, ln_g, ln_b, wk, wv, wq);
    gram_kernel<<<V, H>>>();
    scan_kernel<<<B, H>>>(x, wo, bo, out);
}

// round 15
// speedup vs baseline: 2.2302x; 1.0211x over previous
#include <cuda_runtime.h>
#include <cuda_bf16.h>
#include <cstdint>

// ---------------------------------------------------------------------------
// DeltaOnlyModel: B=256, L=2048, H=V=64.
// Gram-basis state: M = sum_c U[c] k_c^T. State is U (64 x 64 per batch),
// one row per thread in smem. pred = sum_c U[c][i]*G[c][tok] (U row read once
// per quad + broadcast G rows); update = ONE scalar smem RMW per gated token.
// Quad chunking + exact in-quad gate algebra (validated R3/R11).
// ---------------------------------------------------------------------------

#define H 64
#define V 64
#define L 2048
#define B 256
#define USTR 68   // U row stride in floats: 272B = 17x16B -> conflict-free .128

__device__ float g_ktab[V * H];
__device__ float g_vtab[V * H];
__device__ float g_qtab[V * H];
__device__ float g_gram[V * V];     // G[a][b]  = k_a . k_b (symmetric)
__device__ float g_gramqT[V * V];   // GqT[b][a] = k_a . q_b
__device__ float g_thr2[V];

typedef unsigned long long ull;

__device__ __forceinline__ ull ffma2(ull a, ull b, ull c) {
    ull d;
    asm("fma.rn.f32x2 %0, %1, %2, %3;" : "=l"(d) : "l"(a), "l"(b), "l"(c));
    return d;
}
__device__ __forceinline__ ull fadd2(ull a, ull b) {
    ull d;
    asm("add.rn.f32x2 %0, %1, %2;" : "=l"(d) : "l"(a), "l"(b));
    return d;
}
__device__ __forceinline__ ull pack2(float lo, float hi) {
    ull d;
    asm("mov.b64 %0, {%1, %2};" : "=l"(d) : "f"(lo), "f"(hi));
    return d;
}
__device__ __forceinline__ void unpack2(ull a, float& lo, float& hi) {
    asm("mov.b64 {%0, %1}, %2;" : "=f"(lo), "=f"(hi) : "l"(a));
}
__device__ __forceinline__ float hsum2p(ull a, ull b) {
    float lo, hi;
    unpack2(fadd2(a, b), lo, hi);
    return lo + hi;
}

// ---------------------------------------------------------------------------
// Table builder: one block per vocab entry, 64 threads.
// ---------------------------------------------------------------------------
__global__ void build_tables(const float* __restrict__ embed,
                             const float* __restrict__ w1,
                             const float* __restrict__ b1,
                             const float* __restrict__ w2,
                             const float* __restrict__ b2,
                             const float* __restrict__ ln_g,
                             const float* __restrict__ ln_b,
                             const float* __restrict__ wk,
                             const float* __restrict__ wv,
                             const float* __restrict__ wq) {
    __shared__ float se[H];
    __shared__ float su[2 * H];
    __shared__ float sh[H];
    __shared__ float sred[H];

    const int c = blockIdx.x;
    const int j = threadIdx.x;

    se[j] = embed[c * H + j];
    __syncthreads();

    #pragma unroll
    for (int rep = 0; rep < 2; rep++) {
        const int m = j + rep * H;
        float a = b1[m];
        #pragma unroll 8
        for (int i = 0; i < H; i++) a = fmaf(se[i], w1[i * (2 * H) + m], a);
        su[m] = fmaxf(a, 0.0f);
    }
    __syncthreads();

    float f = b2[j];
    #pragma unroll 8
    for (int m = 0; m < 2 * H; m++) f = fmaf(su[m], w2[m * H + j], f);

    const float s = se[j] + f;
    sh[j] = s;
    __syncthreads();

    float mu = 0.0f;
    #pragma unroll 8
    for (int i = 0; i < H; i++) mu += sh[i];
    mu *= (1.0f / H);
    float var = 0.0f;
    #pragma unroll 8
    for (int i = 0; i < H; i++) { float d = sh[i] - mu; var = fmaf(d, d, var); }
    var *= (1.0f / H);
    const float hn = (s - mu) * rsqrtf(var + 1e-5f) * ln_g[j] + ln_b[j];
    __syncthreads();
    sh[j] = hn;
    __syncthreads();

    float kr = 0.0f;
    #pragma unroll 8
    for (int i = 0; i < H; i++) kr = fmaf(sh[i], wk[i * H + j], kr);
    sred[j] = kr * kr;
    __syncthreads();
    float nk = 0.0f;
    #pragma unroll 8
    for (int i = 0; i < H; i++) nk += sred[i];
    nk = fmaxf(sqrtf(nk), 1e-12f);
    g_ktab[c * H + j] = kr / nk;
    __syncthreads();

    float vr = 0.0f;
    #pragma unroll 8
    for (int i = 0; i < H; i++) vr = fmaf(sh[i], wv[i * H + j], vr);
    g_vtab[c * H + j] = vr;
    sred[j] = vr * vr;
    __syncthreads();
    float nv = 0.0f;
    #pragma unroll 8
    for (int i = 0; i < H; i++) nv += sred[i];
    if (j == 0) g_thr2[c] = 0.16f * nv;

    float qr = 0.0f;
    #pragma unroll 8
    for (int i = 0; i < H; i++) qr = fmaf(sh[i], wq[i * H + j], qr);
    g_qtab[c * H + j] = qr;
}

// Gram matrices: G[a][b] = k_a.k_b ; GqT[b][a] = k_a.q_b
__global__ void gram_kernel() {
    __shared__ float ka[H];
    const int a = blockIdx.x;
    const int j = threadIdx.x;
    ka[j] = g_ktab[a * H + j];
    __syncthreads();
    float s = 0.0f, sq = 0.0f;
    #pragma unroll 8
    for (int i = 0; i < H; i++) {
        s  = fmaf(ka[i], g_ktab[j * H + i], s);
        sq = fmaf(ka[i], g_qtab[j * H + i], sq);
    }
    g_gram[a * H + j]   = s;
    g_gramqT[j * H + a] = sq;   // transposed: row b holds k_. q_b
}

// ---------------------------------------------------------------------------
// Scan kernel: Gram-basis state, quad-chunked.
// ---------------------------------------------------------------------------
__global__ __launch_bounds__(64) void scan_kernel(const int* __restrict__ x,
                                                  const float* __restrict__ wo,
                                                  const float* __restrict__ bo,
                                                  float* __restrict__ out) {
    __shared__ __align__(16) float sG[V * V];        // 16 KB Gram
    __shared__ __align__(16) float sU[64 * USTR];    // 17 KB U rows (per thread)
    __shared__ float sthr[V];
    __shared__ int   sx[L];                          // 8 KB tokens
    __shared__ ull   sxA[2][2][5];                   // [parity][warp][5 packed]
    __shared__ float sfin[H];

    const int b    = blockIdx.x;
    const int tid  = threadIdx.x;
    const int lane = tid & 31;
    const int w    = tid >> 5;

    for (int i = tid; i < V * V; i += 64) sG[i] = g_gram[i];
    sthr[tid] = g_thr2[tid];
    const int* xb = x + b * L;
    for (int i = tid; i < L; i += 64) sx[i] = xb[i];

    float* Urow = sU + tid * USTR;
    {
        const float4 z = make_float4(0.f, 0.f, 0.f, 0.f);
        #pragma unroll
        for (int j = 0; j < 16; j++) reinterpret_cast<float4*>(Urow)[j] = z;
    }
    __syncthreads();

    // first-quad state
    int tk0 = sx[0], tk1 = sx[1], tk2 = sx[2], tk3 = sx[3];
    float vv0 = g_vtab[(tk0 << 6) + tid];
    float vv1 = g_vtab[(tk1 << 6) + tid];
    float vv2 = g_vtab[(tk2 << 6) + tid];
    float vv3 = g_vtab[(tk3 << 6) + tid];

    const ulonglong2* Up = reinterpret_cast<const ulonglong2*>(Urow);

    for (int t = 0; t < L; t += 4) {
        // prefetch next quad (tokens + v via L2)
        const int nt = (t + 4) & (L - 1);
        const int nk0 = sx[nt], nk1 = sx[nt + 1], nk2 = sx[nt + 2], nk3 = sx[nt + 3];
        const float nv0 = g_vtab[(nk0 << 6) + tid];
        const float nv1 = g_vtab[(nk1 << 6) + tid];
        const float nv2 = g_vtab[(nk2 << 6) + tid];
        const float nv3 = g_vtab[(nk3 << 6) + tid];

        // gate scalars
        const float thr0 = sthr[tk0], thr1 = sthr[tk1];
        const float thr2 = sthr[tk2], thr3 = sthr[tk3];
        const float G01 = sG[(tk0 << 6) + tk1];
        const float G02 = sG[(tk0 << 6) + tk2];
        const float G03 = sG[(tk0 << 6) + tk3];
        const float G12 = sG[(tk1 << 6) + tk2];
        const float G13 = sG[(tk1 << 6) + tk3];
        const float G23 = sG[(tk2 << 6) + tk3];

        // preds: P_j[i] = sum_c U[c][i] * G[tok_j][c]  (G symmetric)
        const ulonglong2* g0 = reinterpret_cast<const ulonglong2*>(sG + (tk0 << 6));
        const ulonglong2* g1 = reinterpret_cast<const ulonglong2*>(sG + (tk1 << 6));
        const ulonglong2* g2 = reinterpret_cast<const ulonglong2*>(sG + (tk2 << 6));
        const ulonglong2* g3 = reinterpret_cast<const ulonglong2*>(sG + (tk3 << 6));
        ull a0 = 0, a1 = 0, c0 = 0, c1 = 0, e0 = 0, e1 = 0, f0 = 0, f1 = 0;
        #pragma unroll
        for (int j = 0; j < 16; j++) {
            const ulonglong2 uu = Up[j];
            const ulonglong2 G0 = g0[j];
            const ulonglong2 G1 = g1[j];
            const ulonglong2 G2 = g2[j];
            const ulonglong2 G3 = g3[j];
            a0 = ffma2(uu.x, G0.x, a0); a1 = ffma2(uu.y, G0.y, a1);
            c0 = ffma2(uu.x, G1.x, c0); c1 = ffma2(uu.y, G1.y, c1);
            e0 = ffma2(uu.x, G2.x, e0); e1 = ffma2(uu.y, G2.y, e1);
            f0 = ffma2(uu.x, G3.x, f0); f1 = ffma2(uu.y, G3.y, f1);
        }
        const float r0 = vv0 - hsum2p(a0, a1);
        const float r1 = vv1 - hsum2p(c0, c1);
        const float r2 = vv2 - hsum2p(e0, e1);
        const float r3 = vv3 - hsum2p(f0, f1);

        // 10 dot products packed as 5 f32x2, single butterfly phase
        ull u0 = pack2(r0 * r0, r0 * r1);
        ull u1 = pack2(r0 * r2, r0 * r3);
        ull u2 = pack2(r1 * r1, r1 * r2);
        ull u3 = pack2(r1 * r3, r2 * r2);
        ull u4 = pack2(r2 * r3, r3 * r3);
        #pragma unroll
        for (int o = 16; o > 0; o >>= 1) {
            u0 = fadd2(u0, __shfl_xor_sync(0xffffffffu, u0, o));
            u1 = fadd2(u1, __shfl_xor_sync(0xffffffffu, u1, o));
            u2 = fadd2(u2, __shfl_xor_sync(0xffffffffu, u2, o));
            u3 = fadd2(u3, __shfl_xor_sync(0xffffffffu, u3, o));
            u4 = fadd2(u4, __shfl_xor_sync(0xffffffffu, u4, o));
        }
        const int pb = (t >> 2) & 1;
        if (lane == 0) {
            sxA[pb][w][0] = u0; sxA[pb][w][1] = u1; sxA[pb][w][2] = u2;
            sxA[pb][w][3] = u3; sxA[pb][w][4] = u4;
        }
        __syncthreads();
        float S00, S01, S02, S03, S11, S12, S13, S22, S23, S33;
        unpack2(fadd2(sxA[pb][0][0], sxA[pb][1][0]), S00, S01);
        unpack2(fadd2(sxA[pb][0][1], sxA[pb][1][1]), S02, S03);
        unpack2(fadd2(sxA[pb][0][2], sxA[pb][1][2]), S11, S12);
        unpack2(fadd2(sxA[pb][0][3], sxA[pb][1][3]), S13, S22);
        unpack2(fadd2(sxA[pb][0][4], sxA[pb][1][4]), S23, S33);

        // exact in-quad gate algebra (validated R3/R11)
        const bool g0b = S00 > thr0;
        const float w10 = g0b ? -G01 : 0.0f;
        const float n1s = S11 + w10 * (2.0f * S01 + w10 * S00);
        const bool g1b = n1s > thr1;
        const float w21 = g1b ? -G12 : 0.0f;
        const float w20 = (g0b ? -G02 : 0.0f) + w21 * w10;
        const float n2s = S22 + w20 * (w20 * S00 + 2.0f * S02)
                              + w21 * (w21 * S11 + 2.0f * S12)
                              + 2.0f * w20 * w21 * S01;
        const bool g2b = n2s > thr2;
        const float w32 = g2b ? -G23 : 0.0f;
        const float t13 = g1b ? -G13 : 0.0f;
        const float w31 = t13 + w32 * w21;
        const float w30 = (g0b ? -G03 : 0.0f) + t13 * w10 + w32 * w20;
        const float n3s = S33 + w30 * (w30 * S00 + 2.0f * S03)
                              + w31 * (w31 * S11 + 2.0f * S13)
                              + w32 * (w32 * S22 + 2.0f * S23)
                              + 2.0f * (w30 * w31 * S01 + w30 * w32 * S02 + w31 * w32 * S12);
        const bool g3b = n3s > thr3;

        // state update: one scalar RMW per gated token (thread-private row)
        if (g0b | g1b | g2b | g3b) {
            if (g0b) Urow[tk0] += r0;
            if (g1b) Urow[tk1] += fmaf(w10, r0, r1);
            if (g2b) Urow[tk2] += r2 + w20 * r0 + w21 * r1;
            if (g3b) Urow[tk3] += r3 + w30 * r0 + w31 * r1 + w32 * r2;
        }

        tk0 = nk0; tk1 = nk1; tk2 = nk2; tk3 = nk3;
        vv0 = nv0; vv1 = nv1; vv2 = nv2; vv3 = nv3;
    }

    // Readout: read_i = relu( sum_c U[c][i] * (k_c . q_tokL) )
    const int tokL = sx[L - 1];
    const ulonglong2* gq = reinterpret_cast<const ulonglong2*>(g_gramqT + (tokL << 6));
    ull a0 = 0, a1 = 0;
    #pragma unroll
    for (int j = 0; j < 16; j++) {
        const ulonglong2 uu = Up[j];
        const ulonglong2 qq = gq[j];
        a0 = ffma2(uu.x, qq.x, a0);
        a1 = ffma2(uu.y, qq.y, a1);
    }
    sfin[tid] = fmaxf(hsum2p(a0, a1), 0.0f);
    __syncthreads();

    float oacc = bo[tid];
    #pragma unroll 8
    for (int i = 0; i < H; i++) oacc = fmaf(sfin[i], wo[(i << 6) + tid], oacc);
    out[(b << 6) + tid] = oacc;
}

// ---------------------------------------------------------------------------
// Inputs: x, embed, w1, b1, w2, b2, ln_g, ln_b, wk, wv, wq, wo, bo
// ---------------------------------------------------------------------------
extern "C" void kernel_launch(void* const* d_in, const int* in_sizes, int n_in,
                              void* d_out, int out_size) {
    const int*   x     = (const int*)d_in[0];
    const float* embed = (const float*)d_in[1];
    const float* w1    = (const float*)d_in[2];
    const float* b1    = (const float*)d_in[3];
    const float* w2    = (const float*)d_in[4];
    const float* b2    = (const float*)d_in[5];
    const float* ln_g  = (const float*)d_in[6];
    const float* ln_b  = (const float*)d_in[7];
    const float* wk    = (const float*)d_in[8];
    const float* wv    = (const float*)d_in[9];
    const float* wq    = (const float*)d_in[10];
    const float* wo    = (const float*)d_in[11];
    const float* bo    = (const float*)d_in[12];
    float*       out   = (float*)d_out;

    build_tables<<<V, H>>>(embed, w1, b1, w2, b2, ln_g, ln_b, wk, wv, wq);
    gram_kernel<<<V, H>>>();
    scan_kernel<<<B, H>>>(x, wo, bo, out);
}